// round 12
// baseline (speedup 1.0000x reference)
#include <cuda_runtime.h>
#include <cuda_fp16.h>
#include <math.h>
#include <stdint.h>

// ---------------- problem constants ----------------
#define B_    32
#define C_    256
#define HW_   1024
#define NPOS  32768
#define NE    1024
#define EDIM  256
#define EPS_CAND 1.5e-4f
#define CAP   24

// ---------------- device scratch (no allocs allowed) ----------------
__device__ __half g_Bh[(size_t)NE * EDIM];     // 0.5 MB emb in fp16
__device__ int   g_cand[(size_t)NPOS * CAP];   // 3 MB candidate lists
__device__ int   g_ncand[NPOS];
__device__ float g_zsum[NPOS];
__device__ float g_e2[NE];
__device__ int   g_idx[NPOS];
__device__ int   g_counts[NE];
__device__ float g_loss_partial[256];

// ---------------------------------------------------------------------------
__device__ __forceinline__ uint32_t smem_u32(const void* p) {
    uint32_t a;
    asm("{ .reg .u64 t; cvta.to.shared.u64 t, %1; cvt.u32.u64 %0, t; }" : "=r"(a) : "l"(p));
    return a;
}
// order-preserving float->uint encoding for unsigned atomicMin
__device__ __forceinline__ uint32_t fenc(float f) {
    uint32_t u = __float_as_uint(f);
    return (u & 0x80000000u) ? ~u : (u | 0x80000000u);
}
__device__ __forceinline__ float fdec(uint32_t u) {
    return (u & 0x80000000u) ? __uint_as_float(u & 0x7FFFFFFFu)
                             : __uint_as_float(~u);
}
#define SMIN_INIT 0xFF7FFFFFu   // fenc(3.4028235e38f): decodes to +FLT_MAX, NOT NaN

// ---------------------------------------------------------------------------
__global__ void init_kernel() {
    int t = blockIdx.x * blockDim.x + threadIdx.x;
    if (t < NE) g_counts[t] = 0;
}

// exact ||e||^2: sequential fp32, squares rounded separately (matches ref)
__global__ void e2_kernel(const float* __restrict__ emb) {
    int row = blockIdx.x * blockDim.x + threadIdx.x;
    if (row >= NE) return;
    const float* r = emb + (size_t)row * EDIM;
    float s = 0.0f;
    for (int i = 0; i < EDIM; i++) {
        float v = r[i];
        s = __fadd_rn(s, __fmul_rn(v, v));
    }
    g_e2[row] = s;
}

// emb -> fp16 rows
__global__ void conv_e_kernel(const float* __restrict__ emb) {
    int t = blockIdx.x * 256 + threadIdx.x;
    int n = t >> 5, c0 = (t & 31) * 8;
    const float* src = emb + (size_t)n * EDIM + c0;
    __half h[8];
#pragma unroll
    for (int i = 0; i < 8; i++) h[i] = __float2half_rn(src[i]);
    *(uint4*)(&g_Bh[(size_t)n * EDIM + c0]) = *(uint4*)h;
}

// ---------------------------------------------------------------------------
// Fused: z load+transpose+fp16 convert + zsum + HMMA filter GEMM (B double-
// buffered) + stale-min-gated candidate recording + final-min filter.
#define A_STR 264
#define B_STR 264
#define OFF_A     0
#define OFF_B0    33792
#define OFF_B1    67584
#define OFF_STAGE 33792                        // aliases B0+B1 (66560 <= 67584)
#define OFF_CAND  101376                       // int[64*CAP]   = 6144
#define OFF_SC    107520                       // float[64*CAP] = 6144
#define OFF_CNT   113664                       // int[64]
#define OFF_MIN   113920                       // uint[64]
#define GEMM_SMEM 114176

extern __shared__ char gsm[];

__global__ void __launch_bounds__(256, 2)
filter_gemm_kernel(const float* __restrict__ z) {
    __half* As  = (__half*)(gsm + OFF_A);
    __half* Bs0 = (__half*)(gsm + OFF_B0);
    __half* Bs1 = (__half*)(gsm + OFF_B1);
    float* stage = (float*)(gsm + OFF_STAGE);
    int*   sCand = (int*)(gsm + OFF_CAND);
    float* sSc   = (float*)(gsm + OFF_SC);
    int*   sCnt  = (int*)(gsm + OFF_CNT);
    uint32_t* sMin = (uint32_t*)(gsm + OFF_MIN);

    const int tid = threadIdx.x;
    const int lane = tid & 31, wid = tid >> 5;
    const int wm = wid >> 2, wn = wid & 3;    // 2 x 4 warp grid
    const int m0 = blockIdx.x * 64;
    const int b = m0 >> 10, hw0 = m0 & 1023;
    const int g = lane >> 2, t2 = (lane & 3) * 2;
    const unsigned full = 0xFFFFFFFFu;

    // ---- prologue: stage z tile [256 c][64 pos] (pad 65), coalesced ----
    const float* zb = z + (size_t)b * C_ * HW_ + hw0;
    for (int i = tid; i < 4096; i += 256) {
        int c = i >> 4, seg = i & 15;
        float4 v = *(const float4*)(zb + (size_t)c * HW_ + seg * 4);
        float* d = &stage[c * 65 + seg * 4];
        d[0] = v.x; d[1] = v.y; d[2] = v.z; d[3] = v.w;
    }
    __syncthreads();
    // exact zsum: sequential fp32, ascending k, squares rounded separately
    if (tid < 64) {
        float s = 0.0f;
        for (int k = 0; k < EDIM; k++) {
            float v = stage[k * 65 + tid];
            s = __fadd_rn(s, __fmul_rn(v, v));
        }
        g_zsum[m0 + tid] = s;
    }
    // convert to fp16 A tile [row][k]
    for (int i = tid; i < 2048; i += 256) {
        int row = i & 63, u = i >> 6;
        __half h[8];
#pragma unroll
        for (int cc = 0; cc < 8; cc++)
            h[cc] = __float2half_rn(stage[(u * 8 + cc) * 65 + row]);
        *(uint4*)(&As[row * A_STR + u * 8]) = *(uint4*)h;
    }
    __syncthreads();                           // stage dead after this
    if (tid < 64) { sCnt[tid] = 0; sMin[tid] = SMIN_INIT; }

    const uint32_t sA = smem_u32(As);
    const uint32_t sB0 = smem_u32(Bs0), sB1 = smem_u32(Bs1);
    uint32_t aAddr[2], bOff;
#pragma unroll
    for (int i = 0; i < 2; i++)
        aAddr[i] = sA + ((wm * 32 + i * 16 + (lane & 15)) * A_STR + (lane >> 4) * 8) * 2;
    {
        int n = wn * 16 + (lane & 7) + ((lane & 16) ? 8 : 0);
        int seg = (lane & 8) ? 8 : 0;
        bOff = (n * B_STR + seg) * 2;
    }

    // this thread's 4 row-slots (constant across chunks):
    // slot s = i*2 + half -> row wm*32 + i*16 + half*8 + g
    const int rowbase = wm * 32 + g;
    int myrow[4];
#pragma unroll
    for (int s = 0; s < 4; s++) myrow[s] = rowbase + ((s >> 1) * 16) + ((s & 1) * 8);

    // register prefetch of B chunk 0 (64 codes x 256 halves = 2048 uint4)
    uint4 breg[8];
#pragma unroll
    for (int q = 0; q < 8; q++) {
        int l = tid + 256 * q;
        int row = l >> 5, seg = l & 31;
        breg[q] = *(const uint4*)(&g_Bh[(size_t)row * EDIM + seg * 8]);
    }

    for (int nb = 0; nb < 16; nb++) {
        __half* Bcur = (nb & 1) ? Bs1 : Bs0;
        uint32_t bAddr = ((nb & 1) ? sB1 : sB0) + bOff;
#pragma unroll
        for (int q = 0; q < 8; q++) {
            int l = tid + 256 * q;
            int row = l >> 5, seg = l & 31;
            *(uint4*)(&Bcur[row * B_STR + seg * 8]) = breg[q];
        }
        if (nb + 1 < 16) {
#pragma unroll
            for (int q = 0; q < 8; q++) {
                int l = tid + 256 * q;
                int row = l >> 5, seg = l & 31;
                breg[q] = *(const uint4*)(&g_Bh[(size_t)((nb + 1) * 64 + row) * EDIM + seg * 8]);
            }
        }
        __syncthreads();                       // Bcur visible to all warps

        float acc[2][2][4];
#pragma unroll
        for (int i = 0; i < 2; i++)
#pragma unroll
            for (int j = 0; j < 2; j++)
#pragma unroll
                for (int c = 0; c < 4; c++) acc[i][j][c] = 0.0f;

#pragma unroll 4
        for (int kk = 0; kk < 16; kk++) {
            uint32_t a[2][4], bfr[4];
#pragma unroll
            for (int i = 0; i < 2; i++)
                asm volatile("ldmatrix.sync.aligned.m8n8.x4.shared.b16 {%0,%1,%2,%3}, [%4];"
                    : "=r"(a[i][0]), "=r"(a[i][1]), "=r"(a[i][2]), "=r"(a[i][3])
                    : "r"(aAddr[i] + kk * 32));
            asm volatile("ldmatrix.sync.aligned.m8n8.x4.shared.b16 {%0,%1,%2,%3}, [%4];"
                : "=r"(bfr[0]), "=r"(bfr[1]), "=r"(bfr[2]), "=r"(bfr[3])
                : "r"(bAddr + kk * 32));
#pragma unroll
            for (int i = 0; i < 2; i++)
#pragma unroll
                for (int j = 0; j < 2; j++)
                    asm volatile("mma.sync.aligned.m16n8k16.row.col.f32.f16.f16.f32 "
                        "{%0,%1,%2,%3}, {%4,%5,%6,%7}, {%8,%9}, {%0,%1,%2,%3};"
                        : "+f"(acc[i][j][0]), "+f"(acc[i][j][1]),
                          "+f"(acc[i][j][2]), "+f"(acc[i][j][3])
                        : "r"(a[i][0]), "r"(a[i][1]), "r"(a[i][2]), "r"(a[i][3]),
                          "r"(bfr[j * 2]), "r"(bfr[j * 2 + 1]));
        }

        // epilogue: s = e2 - 2*dot. Stale-min gating: cm[s] = sMin at chunk
        // start (>= final min, so sv <= cm+EPS is a SUPERSET of the final
        // candidate condition). atomicMin only when sv improves cm -> rare.
        float cm[4];
#pragma unroll
        for (int s = 0; s < 4; s++)
            cm[s] = fdec(*(volatile uint32_t*)&sMin[myrow[s]]);

#pragma unroll
        for (int i = 0; i < 2; i++)
#pragma unroll
            for (int j = 0; j < 2; j++) {
                int nl = wn * 16 + j * 8 + t2;
                int ng = nb * 64 + nl;
                float e20 = __ldg(&g_e2[ng]), e21 = __ldg(&g_e2[ng + 1]);
                float sv[4];
                sv[0] = __fadd_rn(e20, -(2.0f * acc[i][j][0]));
                sv[1] = __fadd_rn(e21, -(2.0f * acc[i][j][1]));
                sv[2] = __fadd_rn(e20, -(2.0f * acc[i][j][2]));
                sv[3] = __fadd_rn(e21, -(2.0f * acc[i][j][3]));
#pragma unroll
                for (int q = 0; q < 4; q++) {
                    int s = i * 2 + (q >> 1);
                    int col = ng + (q & 1);
                    if (sv[q] <= cm[s] + EPS_CAND) {
                        int row = myrow[s];
                        if (sv[q] < cm[s]) {
                            atomicMin(&sMin[row], fenc(sv[q]));
                            cm[s] = sv[q];
                        }
                        int p = atomicAdd(&sCnt[row], 1);
                        if (p < CAP) {
                            sCand[row * CAP + p] = col;
                            sSc[row * CAP + p] = sv[q];
                        }
                    }
                }
            }
    }
    __syncthreads();

    // final-min filter: warp w handles rows w*8..w*8+7; compact survivors.
    // If cnt > CAP some appends were dropped -> export big ncand (fallback).
    for (int r8 = 0; r8 < 8; r8++) {
        int row = wid * 8 + r8;
        int cnt = sCnt[row];
        if (cnt > CAP) {
            if (lane == 0) g_ncand[m0 + row] = NE;   // full-scan fallback
            continue;
        }
        float thr = fdec(sMin[row]) + EPS_CAND;
        bool keep = (lane < cnt) && (sSc[row * CAP + lane] <= thr);
        unsigned mask = __ballot_sync(full, keep);
        if (keep) {
            int p = __popc(mask & ((1u << lane) - 1));
            g_cand[(size_t)(m0 + row) * CAP + p] = sCand[row * CAP + lane];
        }
        if (lane == 0) g_ncand[m0 + row] = __popc(mask);
    }
}

// ---------------------------------------------------------------------------
// exact rescore of candidates; (score, index) lexicographic min ->
// bit-identical to reference argmin (first-index tie-break).
__global__ void rescore_kernel(const float* __restrict__ z,
                               const float* __restrict__ emb) {
    const int tid = threadIdx.x;
    const int wid = tid >> 5, lane = tid & 31;
    const int m = blockIdx.x * 8 + wid;
    const int b = m >> 10, hw = m & 1023;
    const unsigned full = 0xFFFFFFFFu;

    int nc = g_ncand[m];
    int bestJ;
    if (nc == 1) {
        bestJ = g_cand[(size_t)m * CAP];       // sole candidate is the argmin
    } else {
        float zsum = g_zsum[m];
        const float* zp = z + (size_t)b * C_ * HW_ + hw;
        float bestS = 0.0f; bool have = false; bestJ = -1;
        if (nc >= 2 && nc <= CAP) {
            int ci = lane < nc ? lane : nc - 1;
            int j = g_cand[(size_t)m * CAP + ci];
            const float* ep = emb + (size_t)j * EDIM;
            float acc = 0.0f;
#pragma unroll 8
            for (int k = 0; k < EDIM; k++)
                acc = __fmaf_rn(zp[(size_t)k << 10], ep[k], acc);
            float t1 = __fadd_rn(zsum, __ldg(&g_e2[j]));
            float s  = __fadd_rn(t1, -(2.0f * acc));
            for (int l = 0; l < CAP; l++) {
                float sv = __shfl_sync(full, s, l);
                int   jv = __shfl_sync(full, j, l);
                if (l < nc) {
                    if (!have || sv < bestS || (sv == bestS && jv < bestJ)) {
                        have = true; bestS = sv; bestJ = jv;
                    }
                }
            }
        } else {
            // fallback (overflow or empty): exact argmin over all 1024 codes
            for (int jb = 0; jb < 32; jb++) {
                int j = jb * 32 + lane;
                const float* ep = emb + (size_t)j * EDIM;
                float acc = 0.0f;
#pragma unroll 8
                for (int k = 0; k < EDIM; k++)
                    acc = __fmaf_rn(zp[(size_t)k << 10], ep[k], acc);
                float t1 = __fadd_rn(zsum, __ldg(&g_e2[j]));
                float s  = __fadd_rn(t1, -(2.0f * acc));
                for (int l = 0; l < 32; l++) {
                    float sv = __shfl_sync(full, s, l);
                    int   jv = __shfl_sync(full, j, l);
                    if (!have || sv < bestS || (sv == bestS && jv < bestJ)) {
                        have = true; bestS = sv; bestJ = jv;
                    }
                }
            }
        }
    }
    if (lane == 0) {
        g_idx[m] = bestJ;
        atomicAdd(&g_counts[bestJ], 1);
    }
}

// ---------------------------------------------------------------------------
// scatter z_q (STE rounding replicated) + loss partials; float4 vectorized.
__global__ void scatter_kernel(const float* __restrict__ z,
                               const float* __restrict__ emb,
                               float* __restrict__ out) {
    const int tid = threadIdx.x;
    const int tl = tid & 31, cg = tid >> 5;          // 8 channel groups of 32
    const int pos0 = blockIdx.x * 128 + tl * 4;
    const int b = pos0 >> 10, hw0 = pos0 & 1023;
    int idx4[4];
#pragma unroll
    for (int p = 0; p < 4; p++) idx4[p] = g_idx[pos0 + p];
    const float* zb = z + (size_t)b * C_ * HW_ + (size_t)(cg * 32) * HW_ + hw0;
    float* ob = out + (size_t)b * C_ * HW_ + (size_t)(cg * 32) * HW_ + hw0;
    float lsum = 0.0f;
#pragma unroll 4
    for (int c = 0; c < 32; c++) {
        int cc = cg * 32 + c;
        float4 zv = *(const float4*)(zb + (size_t)c * HW_);
        float4 ov;
        float e0 = __ldg(&emb[(size_t)idx4[0] * EDIM + cc]);
        float e1 = __ldg(&emb[(size_t)idx4[1] * EDIM + cc]);
        float e2v = __ldg(&emb[(size_t)idx4[2] * EDIM + cc]);
        float e3 = __ldg(&emb[(size_t)idx4[3] * EDIM + cc]);
        float d0 = __fadd_rn(e0, -zv.x), d1 = __fadd_rn(e1, -zv.y);
        float d2 = __fadd_rn(e2v, -zv.z), d3 = __fadd_rn(e3, -zv.w);
        lsum += d0 * d0 + d1 * d1 + d2 * d2 + d3 * d3;
        ov.x = __fadd_rn(zv.x, d0); ov.y = __fadd_rn(zv.y, d1);
        ov.z = __fadd_rn(zv.z, d2); ov.w = __fadd_rn(zv.w, d3);
        *(float4*)(ob + (size_t)c * HW_) = ov;
    }
    __shared__ float red[256];
    red[tid] = lsum;
    __syncthreads();
    for (int o = 128; o; o >>= 1) {
        if (tid < o) red[tid] += red[tid + o];
        __syncthreads();
    }
    if (tid == 0) g_loss_partial[blockIdx.x] = red[0];
}

// ---------------------------------------------------------------------------
__global__ void final_kernel(float* __restrict__ out, int out_size) {
    __shared__ float red[256];
    int t = threadIdx.x;
    float ent = 0.0f;
    for (int k = t; k < NE; k += 256) {
        float em = (float)g_counts[k] * (1.0f / (float)NPOS);
        ent += em * logf(em + 1e-10f);
    }
    red[t] = ent;
    __syncthreads();
    for (int o = 128; o; o >>= 1) { if (t < o) red[t] += red[t + o]; __syncthreads(); }
    float perp = expf(-red[0]);
    __syncthreads();
    red[t] = g_loss_partial[t];
    __syncthreads();
    for (int o = 128; o; o >>= 1) { if (t < o) red[t] += red[t + o]; __syncthreads(); }
    if (t == 0) {
        float loss = 1.25f * red[0] * (1.0f / (float)((size_t)NPOS * EDIM));
        out[out_size - 2] = loss;
        out[out_size - 1] = perp;
    }
}

// ---------------------------------------------------------------------------
extern "C" void kernel_launch(void* const* d_in, const int* in_sizes, int n_in,
                              void* d_out, int out_size) {
    const float* z   = (const float*)d_in[0];
    const float* emb = (const float*)d_in[1];
    float* out = (float*)d_out;

    cudaFuncSetAttribute(filter_gemm_kernel,
                         cudaFuncAttributeMaxDynamicSharedMemorySize, GEMM_SMEM);

    init_kernel<<<4, 256>>>();
    e2_kernel<<<4, 256>>>(emb);
    conv_e_kernel<<<128, 256>>>(emb);
    filter_gemm_kernel<<<NPOS / 64, 256, GEMM_SMEM>>>(z);
    rescore_kernel<<<NPOS / 8, 256>>>(z, emb);
    scatter_kernel<<<NPOS / 128, 256>>>(z, emb, out);
    final_kernel<<<1, 256>>>(out, out_size);
}

// round 13
// speedup vs baseline: 143.0356x; 143.0356x over previous
#include <cuda_runtime.h>
#include <cuda_fp16.h>
#include <math.h>
#include <stdint.h>

// ---------------- problem constants ----------------
#define B_    32
#define C_    256
#define HW_   1024
#define NPOS  32768
#define NE    1024
#define EDIM  256
#define EPS_CAND 1.5e-4f
#define CAP   24

// ---------------- device scratch (no allocs allowed) ----------------
__device__ __half g_Bh[(size_t)NE * EDIM];     // 0.5 MB emb in fp16
__device__ int   g_cand[(size_t)NPOS * CAP];   // 3 MB candidate lists
__device__ int   g_ncand[NPOS];
__device__ float g_zsum[NPOS];
__device__ float g_e2[NE];
__device__ int   g_idx[NPOS];
__device__ int   g_counts[NE];
__device__ float g_loss_partial[256];

// ---------------------------------------------------------------------------
__device__ __forceinline__ uint32_t smem_u32(const void* p) {
    uint32_t a;
    asm("{ .reg .u64 t; cvta.to.shared.u64 t, %1; cvt.u32.u64 %0, t; }" : "=r"(a) : "l"(p));
    return a;
}
// order-preserving float->uint encoding for unsigned atomicMin
__device__ __forceinline__ uint32_t fenc(float f) {
    uint32_t u = __float_as_uint(f);
    return (u & 0x80000000u) ? ~u : (u | 0x80000000u);
}
__device__ __forceinline__ float fdec(uint32_t u) {
    return (u & 0x80000000u) ? __uint_as_float(u & 0x7FFFFFFFu)
                             : __uint_as_float(~u);
}
#define SMIN_INIT 0xFF7FFFFFu   // fenc(3.4028235e38f): decodes to +FLT_MAX, NOT NaN

// ---------------------------------------------------------------------------
__global__ void init_kernel() {
    int t = blockIdx.x * blockDim.x + threadIdx.x;
    if (t < NE) g_counts[t] = 0;
}

// exact ||e||^2: sequential fp32, squares rounded separately (matches ref)
__global__ void e2_kernel(const float* __restrict__ emb) {
    int row = blockIdx.x * blockDim.x + threadIdx.x;
    if (row >= NE) return;
    const float* r = emb + (size_t)row * EDIM;
    float s = 0.0f;
    for (int i = 0; i < EDIM; i++) {
        float v = r[i];
        s = __fadd_rn(s, __fmul_rn(v, v));
    }
    g_e2[row] = s;
}

// emb -> fp16 rows
__global__ void conv_e_kernel(const float* __restrict__ emb) {
    int t = blockIdx.x * 256 + threadIdx.x;
    int n = t >> 5, c0 = (t & 31) * 8;
    const float* src = emb + (size_t)n * EDIM + c0;
    __half h[8];
#pragma unroll
    for (int i = 0; i < 8; i++) h[i] = __float2half_rn(src[i]);
    *(uint4*)(&g_Bh[(size_t)n * EDIM + c0]) = *(uint4*)h;
}

// ---------------------------------------------------------------------------
// Fused: z load+transpose+fp16 convert + zsum + HMMA filter GEMM (B double-
// buffered) + hybrid candidate gating:
//   chunk 0:    fresh atomicMin-return path (shared min descends in-chunk)
//   chunks 1+:  stale-min gating (read once/chunk), atomics only on improve
#define A_STR 264
#define B_STR 264
#define OFF_A     0
#define OFF_B0    33792
#define OFF_B1    67584
#define OFF_STAGE 33792                        // aliases B0+B1 (66560 <= 67584)
#define OFF_CAND  101376                       // int[64*CAP]   = 6144
#define OFF_SC    107520                       // float[64*CAP] = 6144
#define OFF_CNT   113664                       // int[64]
#define OFF_MIN   113920                       // uint[64]
#define GEMM_SMEM 114176

extern __shared__ char gsm[];

__global__ void __launch_bounds__(256, 2)
filter_gemm_kernel(const float* __restrict__ z) {
    __half* As  = (__half*)(gsm + OFF_A);
    __half* Bs0 = (__half*)(gsm + OFF_B0);
    __half* Bs1 = (__half*)(gsm + OFF_B1);
    float* stage = (float*)(gsm + OFF_STAGE);
    int*   sCand = (int*)(gsm + OFF_CAND);
    float* sSc   = (float*)(gsm + OFF_SC);
    int*   sCnt  = (int*)(gsm + OFF_CNT);
    uint32_t* sMin = (uint32_t*)(gsm + OFF_MIN);

    const int tid = threadIdx.x;
    const int lane = tid & 31, wid = tid >> 5;
    const int wm = wid >> 2, wn = wid & 3;    // 2 x 4 warp grid
    const int m0 = blockIdx.x * 64;
    const int b = m0 >> 10, hw0 = m0 & 1023;
    const int g = lane >> 2, t2 = (lane & 3) * 2;
    const unsigned full = 0xFFFFFFFFu;

    // ---- prologue: stage z tile [256 c][64 pos] (pad 65), coalesced ----
    const float* zb = z + (size_t)b * C_ * HW_ + hw0;
    for (int i = tid; i < 4096; i += 256) {
        int c = i >> 4, seg = i & 15;
        float4 v = *(const float4*)(zb + (size_t)c * HW_ + seg * 4);
        float* d = &stage[c * 65 + seg * 4];
        d[0] = v.x; d[1] = v.y; d[2] = v.z; d[3] = v.w;
    }
    __syncthreads();
    // exact zsum: sequential fp32, ascending k, squares rounded separately
    if (tid < 64) {
        float s = 0.0f;
        for (int k = 0; k < EDIM; k++) {
            float v = stage[k * 65 + tid];
            s = __fadd_rn(s, __fmul_rn(v, v));
        }
        g_zsum[m0 + tid] = s;
    }
    // convert to fp16 A tile [row][k]
    for (int i = tid; i < 2048; i += 256) {
        int row = i & 63, u = i >> 6;
        __half h[8];
#pragma unroll
        for (int cc = 0; cc < 8; cc++)
            h[cc] = __float2half_rn(stage[(u * 8 + cc) * 65 + row]);
        *(uint4*)(&As[row * A_STR + u * 8]) = *(uint4*)h;
    }
    __syncthreads();                           // stage dead after this
    if (tid < 64) { sCnt[tid] = 0; sMin[tid] = SMIN_INIT; }

    const uint32_t sA = smem_u32(As);
    const uint32_t sB0 = smem_u32(Bs0), sB1 = smem_u32(Bs1);
    uint32_t aAddr[2], bOff;
#pragma unroll
    for (int i = 0; i < 2; i++)
        aAddr[i] = sA + ((wm * 32 + i * 16 + (lane & 15)) * A_STR + (lane >> 4) * 8) * 2;
    {
        int n = wn * 16 + (lane & 7) + ((lane & 16) ? 8 : 0);
        int seg = (lane & 8) ? 8 : 0;
        bOff = (n * B_STR + seg) * 2;
    }

    // this thread's 4 row-slots: slot s -> row wm*32 + (s>>1)*16 + (s&1)*8 + g
    const int rowbase = wm * 32 + g;
    int myrow[4];
#pragma unroll
    for (int s = 0; s < 4; s++) myrow[s] = rowbase + ((s >> 1) * 16) + ((s & 1) * 8);

    // register prefetch of B chunk 0 (64 codes x 256 halves = 2048 uint4)
    uint4 breg[8];
#pragma unroll
    for (int q = 0; q < 8; q++) {
        int l = tid + 256 * q;
        int row = l >> 5, seg = l & 31;
        breg[q] = *(const uint4*)(&g_Bh[(size_t)row * EDIM + seg * 8]);
    }

    for (int nb = 0; nb < 16; nb++) {
        __half* Bcur = (nb & 1) ? Bs1 : Bs0;
        uint32_t bAddr = ((nb & 1) ? sB1 : sB0) + bOff;
#pragma unroll
        for (int q = 0; q < 8; q++) {
            int l = tid + 256 * q;
            int row = l >> 5, seg = l & 31;
            *(uint4*)(&Bcur[row * B_STR + seg * 8]) = breg[q];
        }
        if (nb + 1 < 16) {
#pragma unroll
            for (int q = 0; q < 8; q++) {
                int l = tid + 256 * q;
                int row = l >> 5, seg = l & 31;
                breg[q] = *(const uint4*)(&g_Bh[(size_t)((nb + 1) * 64 + row) * EDIM + seg * 8]);
            }
        }
        __syncthreads();                       // Bcur visible to all warps

        float acc[2][2][4];
#pragma unroll
        for (int i = 0; i < 2; i++)
#pragma unroll
            for (int j = 0; j < 2; j++)
#pragma unroll
                for (int c = 0; c < 4; c++) acc[i][j][c] = 0.0f;

#pragma unroll 4
        for (int kk = 0; kk < 16; kk++) {
            uint32_t a[2][4], bfr[4];
#pragma unroll
            for (int i = 0; i < 2; i++)
                asm volatile("ldmatrix.sync.aligned.m8n8.x4.shared.b16 {%0,%1,%2,%3}, [%4];"
                    : "=r"(a[i][0]), "=r"(a[i][1]), "=r"(a[i][2]), "=r"(a[i][3])
                    : "r"(aAddr[i] + kk * 32));
            asm volatile("ldmatrix.sync.aligned.m8n8.x4.shared.b16 {%0,%1,%2,%3}, [%4];"
                : "=r"(bfr[0]), "=r"(bfr[1]), "=r"(bfr[2]), "=r"(bfr[3])
                : "r"(bAddr + kk * 32));
#pragma unroll
            for (int i = 0; i < 2; i++)
#pragma unroll
                for (int j = 0; j < 2; j++)
                    asm volatile("mma.sync.aligned.m16n8k16.row.col.f32.f16.f16.f32 "
                        "{%0,%1,%2,%3}, {%4,%5,%6,%7}, {%8,%9}, {%0,%1,%2,%3};"
                        : "+f"(acc[i][j][0]), "+f"(acc[i][j][1]),
                          "+f"(acc[i][j][2]), "+f"(acc[i][j][3])
                        : "r"(a[i][0]), "r"(a[i][1]), "r"(a[i][2]), "r"(a[i][3]),
                          "r"(bfr[j * 2]), "r"(bfr[j * 2 + 1]));
        }

        // epilogue: s = e2 - 2*dot. Hybrid gating (superset-safe: any upper
        // bound on the running min yields a candidate SUPERSET).
        float cm[4];
#pragma unroll
        for (int s = 0; s < 4; s++)
            cm[s] = fdec(*(volatile uint32_t*)&sMin[myrow[s]]);

#pragma unroll
        for (int i = 0; i < 2; i++)
#pragma unroll
            for (int j = 0; j < 2; j++) {
                int nl = wn * 16 + j * 8 + t2;
                int ng = nb * 64 + nl;
                float e20 = __ldg(&g_e2[ng]), e21 = __ldg(&g_e2[ng + 1]);
                float sv[4];
                sv[0] = __fadd_rn(e20, -(2.0f * acc[i][j][0]));
                sv[1] = __fadd_rn(e21, -(2.0f * acc[i][j][1]));
                sv[2] = __fadd_rn(e20, -(2.0f * acc[i][j][2]));
                sv[3] = __fadd_rn(e21, -(2.0f * acc[i][j][3]));
#pragma unroll
                for (int q = 0; q < 4; q++) {
                    int s = i * 2 + (q >> 1);
                    int col = ng + (q & 1);
                    int row = myrow[s];
                    if (nb == 0) {
                        // fresh path: shared min descends within the chunk
                        uint32_t old = atomicMin(&sMin[row], fenc(sv[q]));
                        float c = fminf(fdec(old), sv[q]);
                        cm[s] = c;
                        if (sv[q] <= c + EPS_CAND) {
                            int p = atomicAdd(&sCnt[row], 1);
                            if (p < CAP) {
                                sCand[row * CAP + p] = col;
                                sSc[row * CAP + p] = sv[q];
                            }
                        }
                    } else if (sv[q] <= cm[s] + EPS_CAND) {
                        if (sv[q] < cm[s]) {
                            atomicMin(&sMin[row], fenc(sv[q]));
                            cm[s] = sv[q];
                        }
                        int p = atomicAdd(&sCnt[row], 1);
                        if (p < CAP) {
                            sCand[row * CAP + p] = col;
                            sSc[row * CAP + p] = sv[q];
                        }
                    }
                }
            }
    }
    __syncthreads();

    // final-min filter: warp w handles rows w*8..w*8+7; compact survivors.
    // If cnt > CAP some appends were dropped -> export big ncand (fallback).
    for (int r8 = 0; r8 < 8; r8++) {
        int row = wid * 8 + r8;
        int cnt = sCnt[row];
        if (cnt > CAP) {
            if (lane == 0) g_ncand[m0 + row] = NE;   // full-scan fallback
            continue;
        }
        float thr = fdec(sMin[row]) + EPS_CAND;
        bool keep = (lane < cnt) && (sSc[row * CAP + lane] <= thr);
        unsigned mask = __ballot_sync(full, keep);
        if (keep) {
            int p = __popc(mask & ((1u << lane) - 1));
            g_cand[(size_t)(m0 + row) * CAP + p] = sCand[row * CAP + lane];
        }
        if (lane == 0) g_ncand[m0 + row] = __popc(mask);
    }
}

// ---------------------------------------------------------------------------
// exact rescore of candidates; (score, index) lexicographic min ->
// bit-identical to reference argmin (first-index tie-break).
__global__ void rescore_kernel(const float* __restrict__ z,
                               const float* __restrict__ emb) {
    const int tid = threadIdx.x;
    const int wid = tid >> 5, lane = tid & 31;
    const int m = blockIdx.x * 8 + wid;
    const int b = m >> 10, hw = m & 1023;
    const unsigned full = 0xFFFFFFFFu;

    int nc = g_ncand[m];
    int bestJ;
    if (nc == 1) {
        bestJ = g_cand[(size_t)m * CAP];       // sole candidate is the argmin
    } else {
        float zsum = g_zsum[m];
        const float* zp = z + (size_t)b * C_ * HW_ + hw;
        float bestS = 0.0f; bool have = false; bestJ = -1;
        if (nc >= 2 && nc <= CAP) {
            int ci = lane < nc ? lane : nc - 1;
            int j = g_cand[(size_t)m * CAP + ci];
            const float* ep = emb + (size_t)j * EDIM;
            float acc = 0.0f;
#pragma unroll 8
            for (int k = 0; k < EDIM; k++)
                acc = __fmaf_rn(zp[(size_t)k << 10], ep[k], acc);
            float t1 = __fadd_rn(zsum, __ldg(&g_e2[j]));
            float s  = __fadd_rn(t1, -(2.0f * acc));
            for (int l = 0; l < CAP; l++) {
                float sv = __shfl_sync(full, s, l);
                int   jv = __shfl_sync(full, j, l);
                if (l < nc) {
                    if (!have || sv < bestS || (sv == bestS && jv < bestJ)) {
                        have = true; bestS = sv; bestJ = jv;
                    }
                }
            }
        } else {
            // fallback (overflow or empty): exact argmin over all 1024 codes
            for (int jb = 0; jb < 32; jb++) {
                int j = jb * 32 + lane;
                const float* ep = emb + (size_t)j * EDIM;
                float acc = 0.0f;
#pragma unroll 8
                for (int k = 0; k < EDIM; k++)
                    acc = __fmaf_rn(zp[(size_t)k << 10], ep[k], acc);
                float t1 = __fadd_rn(zsum, __ldg(&g_e2[j]));
                float s  = __fadd_rn(t1, -(2.0f * acc));
                for (int l = 0; l < 32; l++) {
                    float sv = __shfl_sync(full, s, l);
                    int   jv = __shfl_sync(full, j, l);
                    if (!have || sv < bestS || (sv == bestS && jv < bestJ)) {
                        have = true; bestS = sv; bestJ = jv;
                    }
                }
            }
        }
    }
    if (lane == 0) {
        g_idx[m] = bestJ;
        atomicAdd(&g_counts[bestJ], 1);
    }
}

// ---------------------------------------------------------------------------
// scatter z_q (STE rounding replicated) + loss partials; float4 vectorized.
__global__ void scatter_kernel(const float* __restrict__ z,
                               const float* __restrict__ emb,
                               float* __restrict__ out) {
    const int tid = threadIdx.x;
    const int tl = tid & 31, cg = tid >> 5;          // 8 channel groups of 32
    const int pos0 = blockIdx.x * 128 + tl * 4;
    const int b = pos0 >> 10, hw0 = pos0 & 1023;
    int idx4[4];
#pragma unroll
    for (int p = 0; p < 4; p++) idx4[p] = g_idx[pos0 + p];
    const float* zb = z + (size_t)b * C_ * HW_ + (size_t)(cg * 32) * HW_ + hw0;
    float* ob = out + (size_t)b * C_ * HW_ + (size_t)(cg * 32) * HW_ + hw0;
    float lsum = 0.0f;
#pragma unroll 4
    for (int c = 0; c < 32; c++) {
        int cc = cg * 32 + c;
        float4 zv = *(const float4*)(zb + (size_t)c * HW_);
        float4 ov;
        float e0 = __ldg(&emb[(size_t)idx4[0] * EDIM + cc]);
        float e1 = __ldg(&emb[(size_t)idx4[1] * EDIM + cc]);
        float e2v = __ldg(&emb[(size_t)idx4[2] * EDIM + cc]);
        float e3 = __ldg(&emb[(size_t)idx4[3] * EDIM + cc]);
        float d0 = __fadd_rn(e0, -zv.x), d1 = __fadd_rn(e1, -zv.y);
        float d2 = __fadd_rn(e2v, -zv.z), d3 = __fadd_rn(e3, -zv.w);
        lsum += d0 * d0 + d1 * d1 + d2 * d2 + d3 * d3;
        ov.x = __fadd_rn(zv.x, d0); ov.y = __fadd_rn(zv.y, d1);
        ov.z = __fadd_rn(zv.z, d2); ov.w = __fadd_rn(zv.w, d3);
        *(float4*)(ob + (size_t)c * HW_) = ov;
    }
    __shared__ float red[256];
    red[tid] = lsum;
    __syncthreads();
    for (int o = 128; o; o >>= 1) {
        if (tid < o) red[tid] += red[tid + o];
        __syncthreads();
    }
    if (tid == 0) g_loss_partial[blockIdx.x] = red[0];
}

// ---------------------------------------------------------------------------
__global__ void final_kernel(float* __restrict__ out, int out_size) {
    __shared__ float red[256];
    int t = threadIdx.x;
    float ent = 0.0f;
    for (int k = t; k < NE; k += 256) {
        float em = (float)g_counts[k] * (1.0f / (float)NPOS);
        ent += em * logf(em + 1e-10f);
    }
    red[t] = ent;
    __syncthreads();
    for (int o = 128; o; o >>= 1) { if (t < o) red[t] += red[t + o]; __syncthreads(); }
    float perp = expf(-red[0]);
    __syncthreads();
    red[t] = g_loss_partial[t];
    __syncthreads();
    for (int o = 128; o; o >>= 1) { if (t < o) red[t] += red[t + o]; __syncthreads(); }
    if (t == 0) {
        float loss = 1.25f * red[0] * (1.0f / (float)((size_t)NPOS * EDIM));
        out[out_size - 2] = loss;
        out[out_size - 1] = perp;
    }
}

// ---------------------------------------------------------------------------
extern "C" void kernel_launch(void* const* d_in, const int* in_sizes, int n_in,
                              void* d_out, int out_size) {
    const float* z   = (const float*)d_in[0];
    const float* emb = (const float*)d_in[1];
    float* out = (float*)d_out;

    cudaFuncSetAttribute(filter_gemm_kernel,
                         cudaFuncAttributeMaxDynamicSharedMemorySize, GEMM_SMEM);

    init_kernel<<<4, 256>>>();
    e2_kernel<<<4, 256>>>(emb);
    conv_e_kernel<<<128, 256>>>(emb);
    filter_gemm_kernel<<<NPOS / 64, 256, GEMM_SMEM>>>(z);
    rescore_kernel<<<NPOS / 8, 256>>>(z, emb);
    scatter_kernel<<<NPOS / 128, 256>>>(z, emb, out);
    final_kernel<<<1, 256>>>(out, out_size);
}

// round 14
// speedup vs baseline: 155.3650x; 1.0862x over previous
#include <cuda_runtime.h>
#include <cuda_fp16.h>
#include <math.h>
#include <stdint.h>

// ---------------- problem constants ----------------
#define B_    32
#define C_    256
#define HW_   1024
#define NPOS  32768
#define NE    1024
#define EDIM  256
#define EPS_CAND 1.5e-4f
#define CAP   24

// ---------------- device scratch (no allocs allowed) ----------------
__device__ __half g_Bh[(size_t)NE * EDIM];     // 0.5 MB emb in fp16
__device__ int   g_cand[(size_t)NPOS * CAP];   // 3 MB candidate lists
__device__ int   g_ncand[NPOS];
__device__ float g_zsum[NPOS];
__device__ float g_e2[NE];
__device__ int   g_idx[NPOS];
__device__ int   g_counts[NE];
__device__ float g_loss_partial[512];

// ---------------------------------------------------------------------------
__device__ __forceinline__ uint32_t smem_u32(const void* p) {
    uint32_t a;
    asm("{ .reg .u64 t; cvta.to.shared.u64 t, %1; cvt.u32.u64 %0, t; }" : "=r"(a) : "l"(p));
    return a;
}
// order-preserving float->uint encoding for unsigned atomicMin
__device__ __forceinline__ uint32_t fenc(float f) {
    uint32_t u = __float_as_uint(f);
    return (u & 0x80000000u) ? ~u : (u | 0x80000000u);
}
__device__ __forceinline__ float fdec(uint32_t u) {
    return (u & 0x80000000u) ? __uint_as_float(u & 0x7FFFFFFFu)
                             : __uint_as_float(~u);
}
#define SMIN_INIT 0xFF7FFFFFu   // fenc(3.4028235e38f): decodes to +FLT_MAX, NOT NaN

// ---------------------------------------------------------------------------
__global__ void init_kernel() {
    int t = blockIdx.x * blockDim.x + threadIdx.x;
    if (t < NE) g_counts[t] = 0;
}

// exact ||e||^2: sequential fp32, squares rounded separately (matches ref)
__global__ void e2_kernel(const float* __restrict__ emb) {
    int row = blockIdx.x * blockDim.x + threadIdx.x;
    if (row >= NE) return;
    const float* r = emb + (size_t)row * EDIM;
    float s = 0.0f;
    for (int i = 0; i < EDIM; i++) {
        float v = r[i];
        s = __fadd_rn(s, __fmul_rn(v, v));
    }
    g_e2[row] = s;
}

// emb -> fp16 rows
__global__ void conv_e_kernel(const float* __restrict__ emb) {
    int t = blockIdx.x * 256 + threadIdx.x;
    int n = t >> 5, c0 = (t & 31) * 8;
    const float* src = emb + (size_t)n * EDIM + c0;
    __half h[8];
#pragma unroll
    for (int i = 0; i < 8; i++) h[i] = __float2half_rn(src[i]);
    *(uint4*)(&g_Bh[(size_t)n * EDIM + c0]) = *(uint4*)h;
}

// ---------------------------------------------------------------------------
// Fused: z load+transpose+fp16 convert + zsum + HMMA filter GEMM (B double-
// buffered) + hybrid candidate gating (chunk 0 fresh, chunks 1+ stale-gated).
#define A_STR 264
#define B_STR 264
#define OFF_A     0
#define OFF_B0    33792
#define OFF_B1    67584
#define OFF_STAGE 33792                        // aliases B0+B1 (66560 <= 67584)
#define OFF_CAND  101376                       // int[64*CAP]   = 6144
#define OFF_SC    107520                       // float[64*CAP] = 6144
#define OFF_CNT   113664                       // int[64]
#define OFF_MIN   113920                       // uint[64]
#define GEMM_SMEM 114176

extern __shared__ char gsm[];

__global__ void __launch_bounds__(256, 2)
filter_gemm_kernel(const float* __restrict__ z) {
    __half* As  = (__half*)(gsm + OFF_A);
    __half* Bs0 = (__half*)(gsm + OFF_B0);
    __half* Bs1 = (__half*)(gsm + OFF_B1);
    float* stage = (float*)(gsm + OFF_STAGE);
    int*   sCand = (int*)(gsm + OFF_CAND);
    float* sSc   = (float*)(gsm + OFF_SC);
    int*   sCnt  = (int*)(gsm + OFF_CNT);
    uint32_t* sMin = (uint32_t*)(gsm + OFF_MIN);

    const int tid = threadIdx.x;
    const int lane = tid & 31, wid = tid >> 5;
    const int wm = wid >> 2, wn = wid & 3;    // 2 x 4 warp grid
    const int m0 = blockIdx.x * 64;
    const int b = m0 >> 10, hw0 = m0 & 1023;
    const int g = lane >> 2, t2 = (lane & 3) * 2;
    const unsigned full = 0xFFFFFFFFu;

    // ---- prologue: stage z tile [256 c][64 pos] (pad 65), coalesced ----
    const float* zb = z + (size_t)b * C_ * HW_ + hw0;
    for (int i = tid; i < 4096; i += 256) {
        int c = i >> 4, seg = i & 15;
        float4 v = *(const float4*)(zb + (size_t)c * HW_ + seg * 4);
        float* d = &stage[c * 65 + seg * 4];
        d[0] = v.x; d[1] = v.y; d[2] = v.z; d[3] = v.w;
    }
    __syncthreads();
    // exact zsum: sequential fp32, ascending k, squares rounded separately
    if (tid < 64) {
        float s = 0.0f;
        for (int k = 0; k < EDIM; k++) {
            float v = stage[k * 65 + tid];
            s = __fadd_rn(s, __fmul_rn(v, v));
        }
        g_zsum[m0 + tid] = s;
    }
    // convert to fp16 A tile [row][k]
    for (int i = tid; i < 2048; i += 256) {
        int row = i & 63, u = i >> 6;
        __half h[8];
#pragma unroll
        for (int cc = 0; cc < 8; cc++)
            h[cc] = __float2half_rn(stage[(u * 8 + cc) * 65 + row]);
        *(uint4*)(&As[row * A_STR + u * 8]) = *(uint4*)h;
    }
    __syncthreads();                           // stage dead after this
    if (tid < 64) { sCnt[tid] = 0; sMin[tid] = SMIN_INIT; }

    const uint32_t sA = smem_u32(As);
    const uint32_t sB0 = smem_u32(Bs0), sB1 = smem_u32(Bs1);
    uint32_t aAddr[2], bOff;
#pragma unroll
    for (int i = 0; i < 2; i++)
        aAddr[i] = sA + ((wm * 32 + i * 16 + (lane & 15)) * A_STR + (lane >> 4) * 8) * 2;
    {
        int n = wn * 16 + (lane & 7) + ((lane & 16) ? 8 : 0);
        int seg = (lane & 8) ? 8 : 0;
        bOff = (n * B_STR + seg) * 2;
    }

    // this thread's 4 row-slots: slot s -> row wm*32 + (s>>1)*16 + (s&1)*8 + g
    const int rowbase = wm * 32 + g;
    int myrow[4];
#pragma unroll
    for (int s = 0; s < 4; s++) myrow[s] = rowbase + ((s >> 1) * 16) + ((s & 1) * 8);

    // register prefetch of B chunk 0 (64 codes x 256 halves = 2048 uint4)
    uint4 breg[8];
#pragma unroll
    for (int q = 0; q < 8; q++) {
        int l = tid + 256 * q;
        int row = l >> 5, seg = l & 31;
        breg[q] = *(const uint4*)(&g_Bh[(size_t)row * EDIM + seg * 8]);
    }

    for (int nb = 0; nb < 16; nb++) {
        __half* Bcur = (nb & 1) ? Bs1 : Bs0;
        uint32_t bAddr = ((nb & 1) ? sB1 : sB0) + bOff;
#pragma unroll
        for (int q = 0; q < 8; q++) {
            int l = tid + 256 * q;
            int row = l >> 5, seg = l & 31;
            *(uint4*)(&Bcur[row * B_STR + seg * 8]) = breg[q];
        }
        if (nb + 1 < 16) {
#pragma unroll
            for (int q = 0; q < 8; q++) {
                int l = tid + 256 * q;
                int row = l >> 5, seg = l & 31;
                breg[q] = *(const uint4*)(&g_Bh[(size_t)((nb + 1) * 64 + row) * EDIM + seg * 8]);
            }
        }
        __syncthreads();                       // Bcur visible to all warps

        float acc[2][2][4];
#pragma unroll
        for (int i = 0; i < 2; i++)
#pragma unroll
            for (int j = 0; j < 2; j++)
#pragma unroll
                for (int c = 0; c < 4; c++) acc[i][j][c] = 0.0f;

#pragma unroll 4
        for (int kk = 0; kk < 16; kk++) {
            uint32_t a[2][4], bfr[4];
#pragma unroll
            for (int i = 0; i < 2; i++)
                asm volatile("ldmatrix.sync.aligned.m8n8.x4.shared.b16 {%0,%1,%2,%3}, [%4];"
                    : "=r"(a[i][0]), "=r"(a[i][1]), "=r"(a[i][2]), "=r"(a[i][3])
                    : "r"(aAddr[i] + kk * 32));
            asm volatile("ldmatrix.sync.aligned.m8n8.x4.shared.b16 {%0,%1,%2,%3}, [%4];"
                : "=r"(bfr[0]), "=r"(bfr[1]), "=r"(bfr[2]), "=r"(bfr[3])
                : "r"(bAddr + kk * 32));
#pragma unroll
            for (int i = 0; i < 2; i++)
#pragma unroll
                for (int j = 0; j < 2; j++)
                    asm volatile("mma.sync.aligned.m16n8k16.row.col.f32.f16.f16.f32 "
                        "{%0,%1,%2,%3}, {%4,%5,%6,%7}, {%8,%9}, {%0,%1,%2,%3};"
                        : "+f"(acc[i][j][0]), "+f"(acc[i][j][1]),
                          "+f"(acc[i][j][2]), "+f"(acc[i][j][3])
                        : "r"(a[i][0]), "r"(a[i][1]), "r"(a[i][2]), "r"(a[i][3]),
                          "r"(bfr[j * 2]), "r"(bfr[j * 2 + 1]));
        }

        // epilogue: s = e2 - 2*dot. Hybrid gating (superset-safe).
        float cm[4];
#pragma unroll
        for (int s = 0; s < 4; s++)
            cm[s] = fdec(*(volatile uint32_t*)&sMin[myrow[s]]);

#pragma unroll
        for (int i = 0; i < 2; i++)
#pragma unroll
            for (int j = 0; j < 2; j++) {
                int nl = wn * 16 + j * 8 + t2;
                int ng = nb * 64 + nl;
                float e20 = __ldg(&g_e2[ng]), e21 = __ldg(&g_e2[ng + 1]);
                float sv[4];
                sv[0] = __fadd_rn(e20, -(2.0f * acc[i][j][0]));
                sv[1] = __fadd_rn(e21, -(2.0f * acc[i][j][1]));
                sv[2] = __fadd_rn(e20, -(2.0f * acc[i][j][2]));
                sv[3] = __fadd_rn(e21, -(2.0f * acc[i][j][3]));
#pragma unroll
                for (int q = 0; q < 4; q++) {
                    int s = i * 2 + (q >> 1);
                    int col = ng + (q & 1);
                    int row = myrow[s];
                    if (nb == 0) {
                        // fresh path: shared min descends within the chunk
                        uint32_t old = atomicMin(&sMin[row], fenc(sv[q]));
                        float c = fminf(fdec(old), sv[q]);
                        cm[s] = c;
                        if (sv[q] <= c + EPS_CAND) {
                            int p = atomicAdd(&sCnt[row], 1);
                            if (p < CAP) {
                                sCand[row * CAP + p] = col;
                                sSc[row * CAP + p] = sv[q];
                            }
                        }
                    } else if (sv[q] <= cm[s] + EPS_CAND) {
                        if (sv[q] < cm[s]) {
                            atomicMin(&sMin[row], fenc(sv[q]));
                            cm[s] = sv[q];
                        }
                        int p = atomicAdd(&sCnt[row], 1);
                        if (p < CAP) {
                            sCand[row * CAP + p] = col;
                            sSc[row * CAP + p] = sv[q];
                        }
                    }
                }
            }
    }
    __syncthreads();

    // final-min filter: warp w handles rows w*8..w*8+7; compact survivors.
    for (int r8 = 0; r8 < 8; r8++) {
        int row = wid * 8 + r8;
        int cnt = sCnt[row];
        if (cnt > CAP) {
            if (lane == 0) g_ncand[m0 + row] = NE;   // full-scan fallback
            continue;
        }
        float thr = fdec(sMin[row]) + EPS_CAND;
        bool keep = (lane < cnt) && (sSc[row * CAP + lane] <= thr);
        unsigned mask = __ballot_sync(full, keep);
        if (keep) {
            int p = __popc(mask & ((1u << lane) - 1));
            g_cand[(size_t)(m0 + row) * CAP + p] = sCand[row * CAP + lane];
        }
        if (lane == 0) g_ncand[m0 + row] = __popc(mask);
    }
}

// ---------------------------------------------------------------------------
// exact rescore of candidates; (score, index) lexicographic min ->
// bit-identical to reference argmin (first-index tie-break).
__global__ void rescore_kernel(const float* __restrict__ z,
                               const float* __restrict__ emb) {
    const int tid = threadIdx.x;
    const int wid = tid >> 5, lane = tid & 31;
    const int m = blockIdx.x * 8 + wid;
    const int b = m >> 10, hw = m & 1023;
    const unsigned full = 0xFFFFFFFFu;

    int nc = g_ncand[m];
    int bestJ;
    if (nc == 1) {
        bestJ = g_cand[(size_t)m * CAP];       // sole candidate is the argmin
    } else {
        float zsum = g_zsum[m];
        const float* zp = z + (size_t)b * C_ * HW_ + hw;
        float bestS = 0.0f; bool have = false; bestJ = -1;
        if (nc >= 2 && nc <= CAP) {
            int ci = lane < nc ? lane : nc - 1;
            int j = g_cand[(size_t)m * CAP + ci];
            const float* ep = emb + (size_t)j * EDIM;
            float acc = 0.0f;
#pragma unroll 8
            for (int k = 0; k < EDIM; k++)
                acc = __fmaf_rn(zp[(size_t)k << 10], ep[k], acc);
            float t1 = __fadd_rn(zsum, __ldg(&g_e2[j]));
            float s  = __fadd_rn(t1, -(2.0f * acc));
            for (int l = 0; l < CAP; l++) {
                float sv = __shfl_sync(full, s, l);
                int   jv = __shfl_sync(full, j, l);
                if (l < nc) {
                    if (!have || sv < bestS || (sv == bestS && jv < bestJ)) {
                        have = true; bestS = sv; bestJ = jv;
                    }
                }
            }
        } else {
            // fallback (overflow or empty): exact argmin over all 1024 codes
            for (int jb = 0; jb < 32; jb++) {
                int j = jb * 32 + lane;
                const float* ep = emb + (size_t)j * EDIM;
                float acc = 0.0f;
#pragma unroll 8
                for (int k = 0; k < EDIM; k++)
                    acc = __fmaf_rn(zp[(size_t)k << 10], ep[k], acc);
                float t1 = __fadd_rn(zsum, __ldg(&g_e2[j]));
                float s  = __fadd_rn(t1, -(2.0f * acc));
                for (int l = 0; l < 32; l++) {
                    float sv = __shfl_sync(full, s, l);
                    int   jv = __shfl_sync(full, j, l);
                    if (!have || sv < bestS || (sv == bestS && jv < bestJ)) {
                        have = true; bestS = sv; bestJ = jv;
                    }
                }
            }
        }
    }
    if (lane == 0) {
        g_idx[m] = bestJ;
        atomicAdd(&g_counts[bestJ], 1);
    }
}

// ---------------------------------------------------------------------------
// scatter z_q + loss partials. Block = 64 positions; stage the block's 64
// selected e-rows in smem (coalesced emb reads), then fully coalesced
// z-read / out-write with conflict-free LDS for e (row stride 257).
__global__ void scatter_kernel(const float* __restrict__ z,
                               const float* __restrict__ emb,
                               float* __restrict__ out) {
    __shared__ float sE[64 * 257];
    __shared__ int sIdx[64];
    __shared__ float red[256];
    const int tid = threadIdx.x;
    const int pos0 = blockIdx.x * 64;
    const int b = pos0 >> 10, hw0 = pos0 & 1023;

    if (tid < 64) sIdx[tid] = g_idx[pos0 + tid];
    __syncthreads();
    // stage e-rows: 64 rows x 256 floats, coalesced float4 from emb
    for (int i = tid; i < 4096; i += 256) {
        int row = i >> 6, seg = i & 63;
        float4 v = *(const float4*)(emb + (size_t)sIdx[row] * EDIM + seg * 4);
        float* d = &sE[row * 257 + seg * 4];
        d[0] = v.x; d[1] = v.y; d[2] = v.z; d[3] = v.w;
    }
    __syncthreads();

    const int tl = tid & 63;          // position lane (64 consecutive positions)
    const int cg = tid >> 6;          // 4 channel groups of 64
    const float* zp = z + (size_t)b * C_ * HW_ + (size_t)(cg * 64) * HW_ + hw0 + tl;
    float* op = out + (size_t)b * C_ * HW_ + (size_t)(cg * 64) * HW_ + hw0 + tl;
    const float* ep = &sE[tl * 257 + cg * 64];
    float lsum = 0.0f;
#pragma unroll 8
    for (int c = 0; c < 64; c++) {
        float zv = zp[(size_t)c * HW_];
        float e  = ep[c];
        float d  = __fadd_rn(e, -zv);
        lsum += d * d;
        op[(size_t)c * HW_] = __fadd_rn(zv, d);   // match reference STE rounding
    }
    red[tid] = lsum;
    __syncthreads();
    for (int o = 128; o; o >>= 1) {
        if (tid < o) red[tid] += red[tid + o];
        __syncthreads();
    }
    if (tid == 0) g_loss_partial[blockIdx.x] = red[0];
}

// ---------------------------------------------------------------------------
__global__ void final_kernel(float* __restrict__ out, int out_size) {
    __shared__ float red[256];
    int t = threadIdx.x;
    float ent = 0.0f;
    for (int k = t; k < NE; k += 256) {
        float em = (float)g_counts[k] * (1.0f / (float)NPOS);
        ent += em * logf(em + 1e-10f);
    }
    red[t] = ent;
    __syncthreads();
    for (int o = 128; o; o >>= 1) { if (t < o) red[t] += red[t + o]; __syncthreads(); }
    float perp = expf(-red[0]);
    __syncthreads();
    red[t] = g_loss_partial[t] + g_loss_partial[t + 256];
    __syncthreads();
    for (int o = 128; o; o >>= 1) { if (t < o) red[t] += red[t + o]; __syncthreads(); }
    if (t == 0) {
        float loss = 1.25f * red[0] * (1.0f / (float)((size_t)NPOS * EDIM));
        out[out_size - 2] = loss;
        out[out_size - 1] = perp;
    }
}

// ---------------------------------------------------------------------------
extern "C" void kernel_launch(void* const* d_in, const int* in_sizes, int n_in,
                              void* d_out, int out_size) {
    const float* z   = (const float*)d_in[0];
    const float* emb = (const float*)d_in[1];
    float* out = (float*)d_out;

    cudaFuncSetAttribute(filter_gemm_kernel,
                         cudaFuncAttributeMaxDynamicSharedMemorySize, GEMM_SMEM);

    init_kernel<<<4, 256>>>();
    e2_kernel<<<4, 256>>>(emb);
    conv_e_kernel<<<128, 256>>>(emb);
    filter_gemm_kernel<<<NPOS / 64, 256, GEMM_SMEM>>>(z);
    rescore_kernel<<<NPOS / 8, 256>>>(z, emb);
    scatter_kernel<<<NPOS / 64, 256>>>(z, emb, out);
    final_kernel<<<1, 256>>>(out, out_size);
}

// round 15
// speedup vs baseline: 155.5778x; 1.0014x over previous
#include <cuda_runtime.h>
#include <cuda_fp16.h>
#include <math.h>
#include <stdint.h>

// ---------------- problem constants ----------------
#define B_    32
#define C_    256
#define HW_   1024
#define NPOS  32768
#define NE    1024
#define EDIM  256
#define EPS_CAND 1.5e-4f
#define F16_GUARD 1e-4f
#define CAP   24

// ---------------- device scratch (no allocs allowed) ----------------
__device__ __half g_Bh[(size_t)NE * EDIM];     // 0.5 MB emb in fp16
__device__ int   g_cand[(size_t)NPOS * CAP];   // 3 MB candidate lists
__device__ int   g_ncand[NPOS];
__device__ float g_zsum[NPOS];
__device__ float g_e2[NE];
__device__ int   g_idx[NPOS];
__device__ int   g_counts[NE];
__device__ float g_loss_partial[512];

// ---------------------------------------------------------------------------
__device__ __forceinline__ uint32_t smem_u32(const void* p) {
    uint32_t a;
    asm("{ .reg .u64 t; cvta.to.shared.u64 t, %1; cvt.u32.u64 %0, t; }" : "=r"(a) : "l"(p));
    return a;
}
// order-preserving float->uint encoding for unsigned atomicMin
__device__ __forceinline__ uint32_t fenc(float f) {
    uint32_t u = __float_as_uint(f);
    return (u & 0x80000000u) ? ~u : (u | 0x80000000u);
}
__device__ __forceinline__ float fdec(uint32_t u) {
    return (u & 0x80000000u) ? __uint_as_float(u & 0x7FFFFFFFu)
                             : __uint_as_float(~u);
}
#define SMIN_INIT 0xFF7FFFFFu   // fenc(FLT_MAX): decodes to +FLT_MAX, NOT NaN

#define CP_ASYNC16(dst, src) \
    asm volatile("cp.async.ca.shared.global [%0], [%1], 16;" :: "r"(dst), "l"(src))
#define CP_COMMIT() asm volatile("cp.async.commit_group;" ::: "memory")
#define CP_WAIT0()  asm volatile("cp.async.wait_group 0;" ::: "memory")

// ---------------------------------------------------------------------------
__global__ void init_kernel() {
    int t = blockIdx.x * blockDim.x + threadIdx.x;
    if (t < NE) g_counts[t] = 0;
}

// exact ||e||^2: sequential fp32, squares rounded separately (matches ref)
__global__ void e2_kernel(const float* __restrict__ emb) {
    int row = blockIdx.x * blockDim.x + threadIdx.x;
    if (row >= NE) return;
    const float* r = emb + (size_t)row * EDIM;
    float s = 0.0f;
    for (int i = 0; i < EDIM; i++) {
        float v = r[i];
        s = __fadd_rn(s, __fmul_rn(v, v));
    }
    g_e2[row] = s;
}

// emb -> fp16 rows
__global__ void conv_e_kernel(const float* __restrict__ emb) {
    int t = blockIdx.x * 256 + threadIdx.x;
    int n = t >> 5, c0 = (t & 31) * 8;
    const float* src = emb + (size_t)n * EDIM + c0;
    __half h[8];
#pragma unroll
    for (int i = 0; i < 8; i++) h[i] = __float2half_rn(src[i]);
    *(uint4*)(&g_Bh[(size_t)n * EDIM + c0]) = *(uint4*)h;
}

// ---------------------------------------------------------------------------
// Fused: z load+transpose+fp16 convert + zsum + HMMA filter GEMM (B streamed
// via cp.async, double-buffered) + hybrid candidate gating + final filter.
#define A_STR 264
#define B_STR 264
#define OFF_A     0
#define OFF_B0    33792
#define OFF_B1    67584
#define OFF_STAGE 33792                        // aliases B0+B1 (66560 <= 67584)
#define OFF_E2    101376                       // float[1024] = 4096
#define OFF_CAND  105472                       // int[64*CAP]   = 6144
#define OFF_SCH   111616                       // half[64*CAP]  = 3072
#define OFF_CNT   114688                       // int[64]
#define OFF_MIN   114944                       // uint[64]
#define GEMM_SMEM 115200

extern __shared__ char gsm[];

__global__ void __launch_bounds__(256, 2)
filter_gemm_kernel(const float* __restrict__ z) {
    __half* As  = (__half*)(gsm + OFF_A);
    float* stage = (float*)(gsm + OFF_STAGE);
    float* e2s   = (float*)(gsm + OFF_E2);
    int*   sCand = (int*)(gsm + OFF_CAND);
    __half* sScH = (__half*)(gsm + OFF_SCH);
    int*   sCnt  = (int*)(gsm + OFF_CNT);
    uint32_t* sMin = (uint32_t*)(gsm + OFF_MIN);

    const int tid = threadIdx.x;
    const int lane = tid & 31, wid = tid >> 5;
    const int wm = wid >> 2, wn = wid & 3;    // 2 x 4 warp grid
    const int m0 = blockIdx.x * 64;
    const int b = m0 >> 10, hw0 = m0 & 1023;
    const int g = lane >> 2, t2 = (lane & 3) * 2;
    const unsigned full = 0xFFFFFFFFu;

    // ---- prologue: stage z tile [256 c][64 pos] (pad 65), coalesced ----
    const float* zb = z + (size_t)b * C_ * HW_ + hw0;
    for (int i = tid; i < 4096; i += 256) {
        int c = i >> 4, seg = i & 15;
        float4 v = *(const float4*)(zb + (size_t)c * HW_ + seg * 4);
        float* d = &stage[c * 65 + seg * 4];
        d[0] = v.x; d[1] = v.y; d[2] = v.z; d[3] = v.w;
    }
    // e2 -> smem (outside alias region, safe here)
    for (int i = tid; i < 1024; i += 256) e2s[i] = g_e2[i];
    __syncthreads();
    // exact zsum: sequential fp32, ascending k, squares rounded separately
    if (tid < 64) {
        float s = 0.0f;
        for (int k = 0; k < EDIM; k++) {
            float v = stage[k * 65 + tid];
            s = __fadd_rn(s, __fmul_rn(v, v));
        }
        g_zsum[m0 + tid] = s;
    }
    // convert to fp16 A tile [row][k]
    for (int i = tid; i < 2048; i += 256) {
        int row = i & 63, u = i >> 6;
        __half h[8];
#pragma unroll
        for (int cc = 0; cc < 8; cc++)
            h[cc] = __float2half_rn(stage[(u * 8 + cc) * 65 + row]);
        *(uint4*)(&As[row * A_STR + u * 8]) = *(uint4*)h;
    }
    __syncthreads();                           // stage dead after this
    if (tid < 64) { sCnt[tid] = 0; sMin[tid] = SMIN_INIT; }

    const uint32_t sA = smem_u32(gsm + OFF_A);
    const uint32_t sB0 = smem_u32(gsm + OFF_B0), sB1 = smem_u32(gsm + OFF_B1);
    uint32_t aAddr[2], bOff;
#pragma unroll
    for (int i = 0; i < 2; i++)
        aAddr[i] = sA + ((wm * 32 + i * 16 + (lane & 15)) * A_STR + (lane >> 4) * 8) * 2;
    {
        int n = wn * 16 + (lane & 7) + ((lane & 16) ? 8 : 0);
        int seg = (lane & 8) ? 8 : 0;
        bOff = (n * B_STR + seg) * 2;
    }

    // this thread's 4 row-slots: slot s -> row wm*32 + (s>>1)*16 + (s&1)*8 + g
    const int rowbase = wm * 32 + g;
    int myrow[4];
#pragma unroll
    for (int s = 0; s < 4; s++) myrow[s] = rowbase + ((s >> 1) * 16) + ((s & 1) * 8);

    // per-thread cp.async slice: 8 x 16B (row = l>>5, seg = l&31)
    const int cprow = tid >> 5;       // base row (stride 8 via q)
    const int cpseg = tid & 31;
    // issue chunk 0 -> B0
#pragma unroll
    for (int q = 0; q < 8; q++) {
        int row = cprow + q * 8;
        uint32_t dst = sB0 + row * (B_STR * 2) + cpseg * 16;
        const char* src = (const char*)g_Bh + (size_t)row * 512 + cpseg * 16;
        CP_ASYNC16(dst, src);
    }
    CP_COMMIT();

    for (int nb = 0; nb < 16; nb++) {
        uint32_t bBuf = (nb & 1) ? sB1 : sB0;
        uint32_t bAddr = bBuf + bOff;
        CP_WAIT0();
        __syncthreads();                       // chunk nb visible; prev reads of other buf done
        if (nb + 1 < 16) {
            uint32_t nBuf = ((nb + 1) & 1) ? sB1 : sB0;
#pragma unroll
            for (int q = 0; q < 8; q++) {
                int row = cprow + q * 8;
                uint32_t dst = nBuf + row * (B_STR * 2) + cpseg * 16;
                const char* src = (const char*)g_Bh
                    + ((size_t)(nb + 1) * 64 + row) * 512 + cpseg * 16;
                CP_ASYNC16(dst, src);
            }
            CP_COMMIT();
        }

        float acc[2][2][4];
#pragma unroll
        for (int i = 0; i < 2; i++)
#pragma unroll
            for (int j = 0; j < 2; j++)
#pragma unroll
                for (int c = 0; c < 4; c++) acc[i][j][c] = 0.0f;

#pragma unroll 4
        for (int kk = 0; kk < 16; kk++) {
            uint32_t a[2][4], bfr[4];
#pragma unroll
            for (int i = 0; i < 2; i++)
                asm volatile("ldmatrix.sync.aligned.m8n8.x4.shared.b16 {%0,%1,%2,%3}, [%4];"
                    : "=r"(a[i][0]), "=r"(a[i][1]), "=r"(a[i][2]), "=r"(a[i][3])
                    : "r"(aAddr[i] + kk * 32));
            asm volatile("ldmatrix.sync.aligned.m8n8.x4.shared.b16 {%0,%1,%2,%3}, [%4];"
                : "=r"(bfr[0]), "=r"(bfr[1]), "=r"(bfr[2]), "=r"(bfr[3])
                : "r"(bAddr + kk * 32));
#pragma unroll
            for (int i = 0; i < 2; i++)
#pragma unroll
                for (int j = 0; j < 2; j++)
                    asm volatile("mma.sync.aligned.m16n8k16.row.col.f32.f16.f16.f32 "
                        "{%0,%1,%2,%3}, {%4,%5,%6,%7}, {%8,%9}, {%0,%1,%2,%3};"
                        : "+f"(acc[i][j][0]), "+f"(acc[i][j][1]),
                          "+f"(acc[i][j][2]), "+f"(acc[i][j][3])
                        : "r"(a[i][0]), "r"(a[i][1]), "r"(a[i][2]), "r"(a[i][3]),
                          "r"(bfr[j * 2]), "r"(bfr[j * 2 + 1]));
        }

        // epilogue: s = e2 - 2*dot. Hybrid gating (superset-safe).
        float cm[4];
#pragma unroll
        for (int s = 0; s < 4; s++)
            cm[s] = fdec(*(volatile uint32_t*)&sMin[myrow[s]]);

#pragma unroll
        for (int i = 0; i < 2; i++)
#pragma unroll
            for (int j = 0; j < 2; j++) {
                int nl = wn * 16 + j * 8 + t2;
                int ng = nb * 64 + nl;
                float e20 = e2s[ng], e21 = e2s[ng + 1];
                float sv[4];
                sv[0] = __fadd_rn(e20, -(2.0f * acc[i][j][0]));
                sv[1] = __fadd_rn(e21, -(2.0f * acc[i][j][1]));
                sv[2] = __fadd_rn(e20, -(2.0f * acc[i][j][2]));
                sv[3] = __fadd_rn(e21, -(2.0f * acc[i][j][3]));
#pragma unroll
                for (int q = 0; q < 4; q++) {
                    int s = i * 2 + (q >> 1);
                    int col = ng + (q & 1);
                    int row = myrow[s];
                    if (nb == 0) {
                        // fresh path: shared min descends within the chunk
                        uint32_t old = atomicMin(&sMin[row], fenc(sv[q]));
                        float c = fminf(fdec(old), sv[q]);
                        cm[s] = c;
                        if (sv[q] <= c + EPS_CAND) {
                            int p = atomicAdd(&sCnt[row], 1);
                            if (p < CAP) {
                                sCand[row * CAP + p] = col;
                                sScH[row * CAP + p] = __float2half_rn(sv[q]);
                            }
                        }
                    } else if (sv[q] <= cm[s] + EPS_CAND) {
                        if (sv[q] < cm[s]) {
                            atomicMin(&sMin[row], fenc(sv[q]));
                            cm[s] = sv[q];
                        }
                        int p = atomicAdd(&sCnt[row], 1);
                        if (p < CAP) {
                            sCand[row * CAP + p] = col;
                            sScH[row * CAP + p] = __float2half_rn(sv[q]);
                        }
                    }
                }
            }
    }
    __syncthreads();

    // final-min filter: warp w handles rows w*8..w*8+7; compact survivors.
    // fp16-stored scores -> widen threshold by F16_GUARD (still a superset).
    for (int r8 = 0; r8 < 8; r8++) {
        int row = wid * 8 + r8;
        int cnt = sCnt[row];
        if (cnt > CAP) {
            if (lane == 0) g_ncand[m0 + row] = NE;   // full-scan fallback
            continue;
        }
        float thr = fdec(sMin[row]) + EPS_CAND + F16_GUARD;
        bool keep = (lane < cnt) && (__half2float(sScH[row * CAP + lane]) <= thr);
        unsigned mask = __ballot_sync(full, keep);
        if (keep) {
            int p = __popc(mask & ((1u << lane) - 1));
            g_cand[(size_t)(m0 + row) * CAP + p] = sCand[row * CAP + lane];
        }
        if (lane == 0) g_ncand[m0 + row] = __popc(mask);
    }
}

// ---------------------------------------------------------------------------
// exact rescore of candidates; (score, index) lexicographic min ->
// bit-identical to reference argmin (first-index tie-break).
__global__ void rescore_kernel(const float* __restrict__ z,
                               const float* __restrict__ emb) {
    const int tid = threadIdx.x;
    const int wid = tid >> 5, lane = tid & 31;
    const int m = blockIdx.x * 8 + wid;
    const int b = m >> 10, hw = m & 1023;
    const unsigned full = 0xFFFFFFFFu;

    int nc = g_ncand[m];
    int bestJ;
    if (nc == 1) {
        bestJ = g_cand[(size_t)m * CAP];       // sole candidate is the argmin
    } else {
        float zsum = g_zsum[m];
        const float* zp = z + (size_t)b * C_ * HW_ + hw;
        float bestS = 0.0f; bool have = false; bestJ = -1;
        if (nc >= 2 && nc <= CAP) {
            int ci = lane < nc ? lane : nc - 1;
            int j = g_cand[(size_t)m * CAP + ci];
            const float* ep = emb + (size_t)j * EDIM;
            float acc = 0.0f;
#pragma unroll 8
            for (int k = 0; k < EDIM; k++)
                acc = __fmaf_rn(zp[(size_t)k << 10], ep[k], acc);
            float t1 = __fadd_rn(zsum, __ldg(&g_e2[j]));
            float s  = __fadd_rn(t1, -(2.0f * acc));
            for (int l = 0; l < CAP; l++) {
                float sv = __shfl_sync(full, s, l);
                int   jv = __shfl_sync(full, j, l);
                if (l < nc) {
                    if (!have || sv < bestS || (sv == bestS && jv < bestJ)) {
                        have = true; bestS = sv; bestJ = jv;
                    }
                }
            }
        } else {
            // fallback (overflow or empty): exact argmin over all 1024 codes
            for (int jb = 0; jb < 32; jb++) {
                int j = jb * 32 + lane;
                const float* ep = emb + (size_t)j * EDIM;
                float acc = 0.0f;
#pragma unroll 8
                for (int k = 0; k < EDIM; k++)
                    acc = __fmaf_rn(zp[(size_t)k << 10], ep[k], acc);
                float t1 = __fadd_rn(zsum, __ldg(&g_e2[j]));
                float s  = __fadd_rn(t1, -(2.0f * acc));
                for (int l = 0; l < 32; l++) {
                    float sv = __shfl_sync(full, s, l);
                    int   jv = __shfl_sync(full, j, l);
                    if (!have || sv < bestS || (sv == bestS && jv < bestJ)) {
                        have = true; bestS = sv; bestJ = jv;
                    }
                }
            }
        }
    }
    if (lane == 0) {
        g_idx[m] = bestJ;
        atomicAdd(&g_counts[bestJ], 1);
    }
}

// ---------------------------------------------------------------------------
// scatter z_q + loss partials; e-rows staged in smem, coalesced z/out.
__global__ void scatter_kernel(const float* __restrict__ z,
                               const float* __restrict__ emb,
                               float* __restrict__ out) {
    __shared__ float sE[64 * 257];
    __shared__ int sIdx[64];
    __shared__ float red[256];
    const int tid = threadIdx.x;
    const int pos0 = blockIdx.x * 64;
    const int b = pos0 >> 10, hw0 = pos0 & 1023;

    if (tid < 64) sIdx[tid] = g_idx[pos0 + tid];
    __syncthreads();
    for (int i = tid; i < 4096; i += 256) {
        int row = i >> 6, seg = i & 63;
        float4 v = *(const float4*)(emb + (size_t)sIdx[row] * EDIM + seg * 4);
        float* d = &sE[row * 257 + seg * 4];
        d[0] = v.x; d[1] = v.y; d[2] = v.z; d[3] = v.w;
    }
    __syncthreads();

    const int tl = tid & 63;
    const int cg = tid >> 6;
    const float* zp = z + (size_t)b * C_ * HW_ + (size_t)(cg * 64) * HW_ + hw0 + tl;
    float* op = out + (size_t)b * C_ * HW_ + (size_t)(cg * 64) * HW_ + hw0 + tl;
    const float* ep = &sE[tl * 257 + cg * 64];
    float lsum = 0.0f;
#pragma unroll 8
    for (int c = 0; c < 64; c++) {
        float zv = zp[(size_t)c * HW_];
        float e  = ep[c];
        float d  = __fadd_rn(e, -zv);
        lsum += d * d;
        op[(size_t)c * HW_] = __fadd_rn(zv, d);
    }
    red[tid] = lsum;
    __syncthreads();
    for (int o = 128; o; o >>= 1) {
        if (tid < o) red[tid] += red[tid + o];
        __syncthreads();
    }
    if (tid == 0) g_loss_partial[blockIdx.x] = red[0];
}

// ---------------------------------------------------------------------------
__global__ void final_kernel(float* __restrict__ out, int out_size) {
    __shared__ float red[256];
    int t = threadIdx.x;
    float ent = 0.0f;
    for (int k = t; k < NE; k += 256) {
        float em = (float)g_counts[k] * (1.0f / (float)NPOS);
        ent += em * logf(em + 1e-10f);
    }
    red[t] = ent;
    __syncthreads();
    for (int o = 128; o; o >>= 1) { if (t < o) red[t] += red[t + o]; __syncthreads(); }
    float perp = expf(-red[0]);
    __syncthreads();
    red[t] = g_loss_partial[t] + g_loss_partial[t + 256];
    __syncthreads();
    for (int o = 128; o; o >>= 1) { if (t < o) red[t] += red[t + o]; __syncthreads(); }
    if (t == 0) {
        float loss = 1.25f * red[0] * (1.0f / (float)((size_t)NPOS * EDIM));
        out[out_size - 2] = loss;
        out[out_size - 1] = perp;
    }
}

// ---------------------------------------------------------------------------
extern "C" void kernel_launch(void* const* d_in, const int* in_sizes, int n_in,
                              void* d_out, int out_size) {
    const float* z   = (const float*)d_in[0];
    const float* emb = (const float*)d_in[1];
    float* out = (float*)d_out;

    cudaFuncSetAttribute(filter_gemm_kernel,
                         cudaFuncAttributeMaxDynamicSharedMemorySize, GEMM_SMEM);

    init_kernel<<<4, 256>>>();
    e2_kernel<<<4, 256>>>(emb);
    conv_e_kernel<<<128, 256>>>(emb);
    filter_gemm_kernel<<<NPOS / 64, 256, GEMM_SMEM>>>(z);
    rescore_kernel<<<NPOS / 8, 256>>>(z, emb);
    scatter_kernel<<<NPOS / 64, 256>>>(z, emb, out);
    final_kernel<<<1, 256>>>(out, out_size);
}